// round 15
// baseline (speedup 1.0000x reference)
#include <cuda_runtime.h>
#include <math.h>

#define B_   64
#define C_   8
#define N_   112
#define LD   113
#define KS   7
#define HALO 3
#define NMAT (B_*C_)
#define NPIX (N_*N_)
#define T_   256
#define EPT  32                /* span width per thread */
#define WPC  (C_*KS*KS)        /* 392 weights per output channel */

typedef unsigned long long ull;

// packed f32x2 helpers (Blackwell packed fp32 math; PTX-only)
__device__ __forceinline__ ull pk2(float x, float y) {
    ull v; asm("mov.b64 %0, {%1,%2};" : "=l"(v) : "f"(x), "f"(y)); return v;
}
__device__ __forceinline__ float lo32(ull v) {
    float x, y; asm("mov.b64 {%0,%1}, %2;" : "=f"(x), "=f"(y) : "l"(v)); return x;
}
__device__ __forceinline__ float hi32(ull v) {
    float x, y; asm("mov.b64 {%0,%1}, %2;" : "=f"(x), "=f"(y) : "l"(v)); return y;
}
#define FFMA2(a, m, s) \
    asm("fma.rn.f32x2 %0, %1, %2, %3;" : "=l"(a) : "l"(m), "l"(s), "l"(a))

// ---------------------------------------------------------------------------
// Register-resident RANK-2 symmetric sweep, f32x2-packed accumulators.
// IDENTICAL to the 159.9us R13 kernel except __launch_bounds__(256,3):
// 85-reg budget -> no spill (A/B test: spill tax vs 1.15-wave tail).
// One CTA per 112x112 SPD matrix; thread owns a 32-wide single-row span
// (i, j0..j0+31) of the lower triangle, packed in areg2[16] (ull).
// Per double-pivot (p,p+1): publish columns p,p+1 into c1v/c2v, barrier,
// update a -= u1*c1[j] + u2*c2[j] via LDS.128 + fma.rn.f32x2, barrier.
// After all pivots: areg = -A^{-1}; rdiag[p]=rsqrt(d11), rdiag[p+1]=rsqrt(det/d11).
// Output: out[i,j] = v1[i,j] * (Ainv[i,j]*rdiag[i] + 1)^2  (both mirrors)
// ---------------------------------------------------------------------------
extern __shared__ float smem[];

__global__ __launch_bounds__(T_, 3)
void fused_kernel(const float* __restrict__ x,
                  const float* __restrict__ w,
                  const float* __restrict__ bias,
                  float* __restrict__ out) {
    float* c1v   = smem;                 // 128 (16B aligned)
    float* c2v   = c1v + 128;            // 128
    float* rdiag = c2v + 128;            // 128
    float* AO    = rdiag + 128;          // N_*LD  (original v1, full)
    float* twv   = AO + N_ * LD;         // WPC tap weights
    int*   tkey  = (int*)(twv + WPC);
    __shared__ int s_ntap;

    const int tid = threadIdx.x;

    // ---- Phase 0: compact nonzero taps of this output channel (warp 0) ----
    {
        const int c = blockIdx.x % C_;
        if (tid < 32) {
            int cnt = 0;
            for (int base = 0; base < WPC; base += 32) {
                const int idx = base + tid;
                const float val = (idx < WPC) ? __ldg(&w[c * WPC + idx]) : 0.0f;
                const unsigned msk = __ballot_sync(0xffffffffu, val != 0.0f);
                if (val != 0.0f) {
                    const int pos = cnt + __popc(msk & ((1u << tid) - 1u));
                    const int ci = idx / (KS * KS);
                    const int r  = idx % (KS * KS);
                    twv[pos]  = val;
                    tkey[pos] = (ci << 16) | ((r / KS) << 8) | (r % KS);
                }
                cnt += __popc(msk);
            }
            if (tid == 0) s_ntap = cnt;
        }
    }
    __syncthreads();

    // ---- Phase 1: conv -> AO ----
    {
        const int b = blockIdx.x / C_;
        const int c = blockIdx.x % C_;
        const float bc = __ldg(&bias[c]);
        const int nt = s_ntap;
        const float* __restrict__ xb = x + (size_t)b * C_ * NPIX;
        for (int p = tid; p < NPIX; p += T_) {
            const int pi = p / N_;
            const int pj = p - pi * N_;
            float acc = bc;
            for (int t = 0; t < nt; ++t) {
                const int key = tkey[t];
                const int ci = key >> 16;
                const int ki = (key >> 8) & 255;
                const int kj = key & 255;
                const int ii = pi + ki - HALO;
                const int jj = pj + kj - HALO;
                if (ii >= 0 && ii < N_ && jj >= 0 && jj < N_)
                    acc += twv[t] * __ldg(&xb[(ci * N_ + ii) * N_ + jj]);
            }
            AO[pi * LD + pj] = acc;
        }
    }
    __syncthreads();

    // ---- span assignment (j0-sorted: warps have uniform j0) ----
    int i, j0;
    if (tid < 112)       { i = tid;        j0 = 0;  }
    else if (tid < 192)  { i = tid - 80;   j0 = 32; }
    else if (tid < 240)  { i = tid - 128;  j0 = 64; }
    else                 { i = tid - 144;  j0 = 96; }

    // ---- load my span into packed registers ----
    ull areg2[EPT / 2];
    {
        const int len = min(EPT, i + 1 - j0);
        #pragma unroll
        for (int k = 0; k < EPT; k += 2) {
            const float a0 = (k < len)     ? AO[i * LD + j0 + k]     : 0.0f;
            const float a1 = (k + 1 < len) ? AO[i * LD + j0 + k + 1] : 0.0f;
            areg2[k >> 1] = pk2(a0, a1);
        }
    }

    // ---- Phase 2: rank-2 symmetric sweep, 56 double-pivots ----
    for (int p = 0; p < N_; p += 2) {
        const int kp = p - j0;          // may be out of [0,EPT)
        const int kq = kp >> 1;
        const bool odd = (kp & 1) != 0;
        // publish pivot columns p (c1v) and p+1 (c2v), pre-step values
        if (i == p) {
            const int len = min(EPT, i + 1 - j0);
            #pragma unroll
            for (int k = 0; k < EPT; k += 2) {
                const ull v = areg2[k >> 1];
                if (k < len)     c1v[j0 + k]     = lo32(v);
                if (k + 1 < len) c1v[j0 + k + 1] = hi32(v);
            }
        } else if (i == p + 1) {
            const int len = min(EPT, i + 1 - j0);
            #pragma unroll
            for (int k = 0; k < EPT; k += 2) {
                const ull v = areg2[k >> 1];
                if (k < len)     c2v[j0 + k]     = lo32(v);
                if (k + 1 < len) c2v[j0 + k + 1] = hi32(v);
            }
        } else if (i > p + 1 && kp >= -1 && kp < EPT) {
            if (!odd) {                 // kp even: both lanes in pair kq
                #pragma unroll
                for (int q = 0; q < EPT / 2; ++q)
                    if (q == kq) {
                        const ull v = areg2[q];
                        c1v[i] = lo32(v);
                        c2v[i] = hi32(v);
                    }
            } else {                    // kp odd: hi of kq, lo of kq+1
                #pragma unroll
                for (int q = 0; q < EPT / 2; ++q) {
                    if (q == kq && kp >= 0)           c1v[i] = hi32(areg2[q]);
                    if (q == kq + 1 && kp + 1 < EPT)  c2v[i] = lo32(areg2[q]);
                }
            }
        }
        __syncthreads();
        const float d11 = c1v[p];
        const float d12 = c2v[p];
        const float d22 = c2v[p + 1];
        const float det = d11 * d22 - d12 * d12;
        const float rdet = 1.0f / det;
        if (tid == p) {                  // thread (i=p, j0=0) always exists
            rdiag[p]     = rsqrtf(d11);
            rdiag[p + 1] = rsqrtf(det / d11);
        }
        if (i == p) {
            #pragma unroll
            for (int k = 0; k < EPT; k += 2) {
                const ull v = areg2[k >> 1];
                float n0 = (d22 * lo32(v) - d12 * c2v[j0 + k])     * rdet;
                float n1 = (d22 * hi32(v) - d12 * c2v[j0 + k + 1]) * rdet;
                if (k == kp)     n0 = -d22 * rdet;
                if (k + 1 == kp) n1 = -d22 * rdet;
                areg2[k >> 1] = pk2(n0, n1);
            }
        } else if (i == p + 1) {
            #pragma unroll
            for (int k = 0; k < EPT; k += 2) {
                const ull v = areg2[k >> 1];
                float n0 = (d11 * lo32(v) - d12 * c1v[j0 + k])     * rdet;
                float n1 = (d11 * hi32(v) - d12 * c1v[j0 + k + 1]) * rdet;
                if (k == kp)         n0 = d12 * rdet;     // col p
                if (k + 1 == kp)     n1 = d12 * rdet;     // col p
                if (k == kp + 1)     n0 = -d11 * rdet;    // col p+1 (diag)
                if (k + 1 == kp + 1) n1 = -d11 * rdet;    // col p+1 (diag)
                areg2[k >> 1] = pk2(n0, n1);
            }
        } else {
            const float c1i = c1v[i];
            const float c2i = c2v[i];
            const float u1 = (c1i * d22 - c2i * d12) * rdet;
            const float u2 = (c2i * d11 - c1i * d12) * rdet;
            const ull nu1 = pk2(-u1, -u1);
            const ull nu2 = pk2(-u2, -u2);
            const ulonglong2* __restrict__ C1 = (const ulonglong2*)(c1v + j0);
            const ulonglong2* __restrict__ C2 = (const ulonglong2*)(c2v + j0);
            #pragma unroll
            for (int k = 0; k < EPT; k += 4) {
                const ulonglong2 w1 = C1[k >> 2];
                const ulonglong2 w2 = C2[k >> 2];
                FFMA2(areg2[k >> 1],       nu2, w2.x);
                FFMA2(areg2[k >> 1],       nu1, w1.x);
                FFMA2(areg2[(k >> 1) + 1], nu2, w2.y);
                FFMA2(areg2[(k >> 1) + 1], nu1, w1.y);
            }
            if (i > p + 1 && kp >= -1 && kp < EPT) {
                if (!odd) {             // kp even: whole pair kq = (u1,u2)
                    const ull pu = pk2(u1, u2);
                    #pragma unroll
                    for (int q = 0; q < EPT / 2; ++q)
                        if (q == kq) areg2[q] = pu;
                } else {                // kp odd: hi of kq = u1, lo of kq+1 = u2
                    #pragma unroll
                    for (int q = 0; q < EPT / 2; ++q) {
                        if (q == kq && kp >= 0)
                            areg2[q] = pk2(lo32(areg2[q]), u1);
                        if (q == kq + 1 && kp + 1 < EPT)
                            areg2[q] = pk2(u2, hi32(areg2[q]));
                    }
                }
            }
        }
        __syncthreads();
    }

    // ---- Phase 3: fused elementwise output (both mirrors per element) ----
    {
        float* __restrict__ O = out + (size_t)blockIdx.x * NPIX;
        const int len = min(EPT, i + 1 - j0);
        const float ri = rdiag[i];
        #pragma unroll
        for (int k = 0; k < EPT; ++k) {
            if (k < len) {
                const int j = j0 + k;
                const ull pv = areg2[k >> 1];
                const float ainv = -((k & 1) ? hi32(pv) : lo32(pv));
                const float rj = rdiag[j];
                const float alo = AO[i * LD + j];
                const float ahi = AO[j * LD + i];
                const float u = fmaf(ainv, ri, 1.0f);
                const float v = fmaf(ainv, rj, 1.0f);
                O[i * N_ + j] = alo * u * u;
                O[j * N_ + i] = ahi * v * v;
            }
        }
    }
}

// ---------------------------------------------------------------------------
extern "C" void kernel_launch(void* const* d_in, const int* in_sizes, int n_in,
                              void* d_out, int out_size) {
    const float* x1   = (const float*)d_in[0];
    const float* w    = (const float*)d_in[1];
    const float* bias = (const float*)d_in[2];
    float* out = (float*)d_out;
    (void)in_sizes; (void)n_in; (void)out_size;

    static const int SMEM_BYTES =
        (int)((384 + N_ * LD + WPC) * sizeof(float) + WPC * sizeof(int));

    cudaFuncSetAttribute(fused_kernel,
                         cudaFuncAttributeMaxDynamicSharedMemorySize,
                         SMEM_BYTES);

    fused_kernel<<<NMAT, T_, SMEM_BYTES>>>(x1, w, bias, out);
}

// round 16
// speedup vs baseline: 1.0025x; 1.0025x over previous
#include <cuda_runtime.h>
#include <math.h>

#define B_   64
#define C_   8
#define N_   112
#define LD   113
#define KS   7
#define HALO 3
#define NMAT (B_*C_)
#define NPIX (N_*N_)
#define T_   320
#define EPT  24                /* span width per thread */
#define WPC  (C_*KS*KS)        /* 392 weights per output channel */

typedef unsigned long long ull;

// packed f32x2 helpers (Blackwell packed fp32 math; PTX-only)
__device__ __forceinline__ ull pk2(float x, float y) {
    ull v; asm("mov.b64 %0, {%1,%2};" : "=l"(v) : "f"(x), "f"(y)); return v;
}
__device__ __forceinline__ float lo32(ull v) {
    float x, y; asm("mov.b64 {%0,%1}, %2;" : "=f"(x), "=f"(y) : "l"(v)); return x;
}
__device__ __forceinline__ float hi32(ull v) {
    float x, y; asm("mov.b64 {%0,%1}, %2;" : "=f"(x), "=f"(y) : "l"(v)); return y;
}
#define FFMA2(a, m, s) \
    asm("fma.rn.f32x2 %0, %1, %2, %3;" : "=l"(a) : "l"(m), "l"(s), "l"(a))

// ---------------------------------------------------------------------------
// Register-resident RANK-2 symmetric sweep, f32x2 accumulators.
// Re-tiled from the 159.9us kernel: EPT=24, 320 threads, 4 CTAs/SM with
// NO spill (~46 regs < 51-reg budget) and 25% more warps for hiding.
// One CTA per 112x112 SPD matrix; thread owns a 24-wide single-row span
// (i, j0..j0+23) of the lower triangle, packed in areg2[12] (ull).
// Per double-pivot (p,p+1): publish columns p,p+1 into c1v/c2v, barrier,
// update a -= u1*c1[j] + u2*c2[j] via LDS.128 + fma.rn.f32x2, barrier.
// After all pivots: areg = -A^{-1}; rdiag[p]=rsqrt(d11), rdiag[p+1]=rsqrt(det/d11).
// Output: out[i,j] = v1[i,j] * (Ainv[i,j]*rdiag[i] + 1)^2  (both mirrors)
// ---------------------------------------------------------------------------
extern __shared__ float smem[];

__global__ __launch_bounds__(T_, 4)
void fused_kernel(const float* __restrict__ x,
                  const float* __restrict__ w,
                  const float* __restrict__ bias,
                  float* __restrict__ out) {
    float* c1v   = smem;                 // 128 (16B aligned)
    float* c2v   = c1v + 128;            // 128
    float* rdiag = c2v + 128;            // 128
    float* AO    = rdiag + 128;          // N_*LD  (original v1, full)
    float* twv   = AO + N_ * LD;         // WPC tap weights
    int*   tkey  = (int*)(twv + WPC);
    __shared__ int s_ntap;

    const int tid = threadIdx.x;

    // ---- Phase 0: compact nonzero taps of this output channel (warp 0) ----
    {
        const int c = blockIdx.x % C_;
        if (tid < 32) {
            int cnt = 0;
            for (int base = 0; base < WPC; base += 32) {
                const int idx = base + tid;
                const float val = (idx < WPC) ? __ldg(&w[c * WPC + idx]) : 0.0f;
                const unsigned msk = __ballot_sync(0xffffffffu, val != 0.0f);
                if (val != 0.0f) {
                    const int pos = cnt + __popc(msk & ((1u << tid) - 1u));
                    const int ci = idx / (KS * KS);
                    const int r  = idx % (KS * KS);
                    twv[pos]  = val;
                    tkey[pos] = (ci << 16) | ((r / KS) << 8) | (r % KS);
                }
                cnt += __popc(msk);
            }
            if (tid == 0) s_ntap = cnt;
        }
    }
    __syncthreads();

    // ---- Phase 1: conv -> AO ----
    {
        const int b = blockIdx.x / C_;
        const int c = blockIdx.x % C_;
        const float bc = __ldg(&bias[c]);
        const int nt = s_ntap;
        const float* __restrict__ xb = x + (size_t)b * C_ * NPIX;
        for (int p = tid; p < NPIX; p += T_) {
            const int pi = p / N_;
            const int pj = p - pi * N_;
            float acc = bc;
            for (int t = 0; t < nt; ++t) {
                const int key = tkey[t];
                const int ci = key >> 16;
                const int ki = (key >> 8) & 255;
                const int kj = key & 255;
                const int ii = pi + ki - HALO;
                const int jj = pj + kj - HALO;
                if (ii >= 0 && ii < N_ && jj >= 0 && jj < N_)
                    acc += twv[t] * __ldg(&xb[(ci * N_ + ii) * N_ + jj]);
            }
            AO[pi * LD + pj] = acc;
        }
    }
    __syncthreads();

    // ---- span assignment (j0-sorted; 320 spans cover the triangle) ----
    int i, j0;
    if (tid < 112)       { i = tid;        j0 = 0;  }
    else if (tid < 200)  { i = tid - 88;   j0 = 24; }
    else if (tid < 264)  { i = tid - 152;  j0 = 48; }
    else if (tid < 304)  { i = tid - 192;  j0 = 72; }
    else                 { i = tid - 208;  j0 = 96; }

    // ---- load my span into packed registers ----
    ull areg2[EPT / 2];
    {
        const int len = min(EPT, i + 1 - j0);
        #pragma unroll
        for (int k = 0; k < EPT; k += 2) {
            const float a0 = (k < len)     ? AO[i * LD + j0 + k]     : 0.0f;
            const float a1 = (k + 1 < len) ? AO[i * LD + j0 + k + 1] : 0.0f;
            areg2[k >> 1] = pk2(a0, a1);
        }
    }

    // ---- Phase 2: rank-2 symmetric sweep, 56 double-pivots ----
    for (int p = 0; p < N_; p += 2) {
        const int kp = p - j0;          // may be out of [0,EPT)
        const int kq = kp >> 1;
        const bool odd = (kp & 1) != 0;
        // publish pivot columns p (c1v) and p+1 (c2v), pre-step values
        if (i == p) {
            const int len = min(EPT, i + 1 - j0);
            #pragma unroll
            for (int k = 0; k < EPT; k += 2) {
                const ull v = areg2[k >> 1];
                if (k < len)     c1v[j0 + k]     = lo32(v);
                if (k + 1 < len) c1v[j0 + k + 1] = hi32(v);
            }
        } else if (i == p + 1) {
            const int len = min(EPT, i + 1 - j0);
            #pragma unroll
            for (int k = 0; k < EPT; k += 2) {
                const ull v = areg2[k >> 1];
                if (k < len)     c2v[j0 + k]     = lo32(v);
                if (k + 1 < len) c2v[j0 + k + 1] = hi32(v);
            }
        } else if (i > p + 1 && kp >= -1 && kp < EPT) {
            if (!odd) {                 // kp even: both lanes in pair kq
                #pragma unroll
                for (int q = 0; q < EPT / 2; ++q)
                    if (q == kq) {
                        const ull v = areg2[q];
                        c1v[i] = lo32(v);
                        c2v[i] = hi32(v);
                    }
            } else {                    // kp odd: hi of kq, lo of kq+1
                #pragma unroll
                for (int q = 0; q < EPT / 2; ++q) {
                    if (q == kq && kp >= 0)           c1v[i] = hi32(areg2[q]);
                    if (q == kq + 1 && kp + 1 < EPT)  c2v[i] = lo32(areg2[q]);
                }
            }
        }
        __syncthreads();
        const float d11 = c1v[p];
        const float d12 = c2v[p];
        const float d22 = c2v[p + 1];
        const float det = d11 * d22 - d12 * d12;
        const float rdet = 1.0f / det;
        if (tid == p) {                  // thread (i=p, j0=0) always exists
            rdiag[p]     = rsqrtf(d11);
            rdiag[p + 1] = rsqrtf(det / d11);
        }
        if (i == p) {
            #pragma unroll
            for (int k = 0; k < EPT; k += 2) {
                const ull v = areg2[k >> 1];
                float n0 = (d22 * lo32(v) - d12 * c2v[j0 + k])     * rdet;
                float n1 = (d22 * hi32(v) - d12 * c2v[j0 + k + 1]) * rdet;
                if (k == kp)     n0 = -d22 * rdet;
                if (k + 1 == kp) n1 = -d22 * rdet;
                areg2[k >> 1] = pk2(n0, n1);
            }
        } else if (i == p + 1) {
            #pragma unroll
            for (int k = 0; k < EPT; k += 2) {
                const ull v = areg2[k >> 1];
                float n0 = (d11 * lo32(v) - d12 * c1v[j0 + k])     * rdet;
                float n1 = (d11 * hi32(v) - d12 * c1v[j0 + k + 1]) * rdet;
                if (k == kp)         n0 = d12 * rdet;     // col p
                if (k + 1 == kp)     n1 = d12 * rdet;     // col p
                if (k == kp + 1)     n0 = -d11 * rdet;    // col p+1 (diag)
                if (k + 1 == kp + 1) n1 = -d11 * rdet;    // col p+1 (diag)
                areg2[k >> 1] = pk2(n0, n1);
            }
        } else {
            const float c1i = c1v[i];
            const float c2i = c2v[i];
            const float u1 = (c1i * d22 - c2i * d12) * rdet;
            const float u2 = (c2i * d11 - c1i * d12) * rdet;
            const ull nu1 = pk2(-u1, -u1);
            const ull nu2 = pk2(-u2, -u2);
            const ulonglong2* __restrict__ C1 = (const ulonglong2*)(c1v + j0);
            const ulonglong2* __restrict__ C2 = (const ulonglong2*)(c2v + j0);
            #pragma unroll
            for (int k = 0; k < EPT; k += 4) {
                const ulonglong2 w1 = C1[k >> 2];
                const ulonglong2 w2 = C2[k >> 2];
                FFMA2(areg2[k >> 1],       nu2, w2.x);
                FFMA2(areg2[k >> 1],       nu1, w1.x);
                FFMA2(areg2[(k >> 1) + 1], nu2, w2.y);
                FFMA2(areg2[(k >> 1) + 1], nu1, w1.y);
            }
            if (i > p + 1 && kp >= -1 && kp < EPT) {
                if (!odd) {             // kp even: whole pair kq = (u1,u2)
                    const ull pu = pk2(u1, u2);
                    #pragma unroll
                    for (int q = 0; q < EPT / 2; ++q)
                        if (q == kq) areg2[q] = pu;
                } else {                // kp odd: hi of kq = u1, lo of kq+1 = u2
                    #pragma unroll
                    for (int q = 0; q < EPT / 2; ++q) {
                        if (q == kq && kp >= 0)
                            areg2[q] = pk2(lo32(areg2[q]), u1);
                        if (q == kq + 1 && kp + 1 < EPT)
                            areg2[q] = pk2(u2, hi32(areg2[q]));
                    }
                }
            }
        }
        __syncthreads();
    }

    // ---- Phase 3: fused elementwise output (both mirrors per element) ----
    {
        float* __restrict__ O = out + (size_t)blockIdx.x * NPIX;
        const int len = min(EPT, i + 1 - j0);
        const float ri = rdiag[i];
        #pragma unroll
        for (int k = 0; k < EPT; ++k) {
            if (k < len) {
                const int j = j0 + k;
                const ull pv = areg2[k >> 1];
                const float ainv = -((k & 1) ? hi32(pv) : lo32(pv));
                const float rj = rdiag[j];
                const float alo = AO[i * LD + j];
                const float ahi = AO[j * LD + i];
                const float u = fmaf(ainv, ri, 1.0f);
                const float v = fmaf(ainv, rj, 1.0f);
                O[i * N_ + j] = alo * u * u;
                O[j * N_ + i] = ahi * v * v;
            }
        }
    }
}

// ---------------------------------------------------------------------------
extern "C" void kernel_launch(void* const* d_in, const int* in_sizes, int n_in,
                              void* d_out, int out_size) {
    const float* x1   = (const float*)d_in[0];
    const float* w    = (const float*)d_in[1];
    const float* bias = (const float*)d_in[2];
    float* out = (float*)d_out;
    (void)in_sizes; (void)n_in; (void)out_size;

    static const int SMEM_BYTES =
        (int)((384 + N_ * LD + WPC) * sizeof(float) + WPC * sizeof(int));

    cudaFuncSetAttribute(fused_kernel,
                         cudaFuncAttributeMaxDynamicSharedMemorySize,
                         SMEM_BYTES);

    fused_kernel<<<NMAT, T_, SMEM_BYTES>>>(x1, w, bias, out);
}

// round 17
// speedup vs baseline: 1.2839x; 1.2807x over previous
#include <cuda_runtime.h>
#include <math.h>

#define B_   64
#define C_   8
#define N_   112
#define LD   113
#define KS   7
#define HALO 3
#define NMAT (B_*C_)
#define NPIX (N_*N_)
#define T_   256
#define EPT  32                /* span width per thread */
#define WPC  (C_*KS*KS)        /* 392 weights per output channel */

typedef unsigned long long ull;

// packed f32x2 helpers (Blackwell packed fp32 math; PTX-only)
__device__ __forceinline__ ull pk2(float x, float y) {
    ull v; asm("mov.b64 %0, {%1,%2};" : "=l"(v) : "f"(x), "f"(y)); return v;
}
__device__ __forceinline__ float lo32(ull v) {
    float x, y; asm("mov.b64 {%0,%1}, %2;" : "=f"(x), "=f"(y) : "l"(v)); return x;
}
__device__ __forceinline__ float hi32(ull v) {
    float x, y; asm("mov.b64 {%0,%1}, %2;" : "=f"(x), "=f"(y) : "l"(v)); return y;
}
#define FFMA2(a, m, s) \
    asm("fma.rn.f32x2 %0, %1, %2, %3;" : "=l"(a) : "l"(m), "l"(s), "l"(a))

// ---------------------------------------------------------------------------
// Register-resident RANK-2 symmetric sweep, f32x2 accumulators, UNIFIED
// branch-free update path. Config = 159.9us champion (256 thr, EPT=32, 4/SM).
// Thread owns span (i, j0..j0+31); j0 in {0,32,64,96}, p even => kp = p-j0
// always EVEN: columns p,p+1 are the lo/hi lanes of the single pair kq.
// Pivot-row updates folded into the generic form  a -= u1*c1[j] + u2*c2[j]:
//   i==p  : u1 = 1-d22*rdet, u2 = d12*rdet      (a = c1[j])
//   i==p+1: u1 = d12*rdet,   u2 = 1-d11*rdet    (a = c2[j])
//   else  : (u1,u2) = (c1[i],c2[i]) * D^{-1}
// Column-p/p+1 fixup writes ONE ull: (f1,f2) per the block-sweep rules.
// After all pivots: areg = -A^{-1}; rdiag[p]=rsqrt(d11), rdiag[p+1]=rsqrt(det/d11).
// Output: out[i,j] = v1[i,j] * (Ainv[i,j]*rdiag[i] + 1)^2  (both mirrors)
// ---------------------------------------------------------------------------
extern __shared__ float smem[];

__global__ __launch_bounds__(T_, 4)
void fused_kernel(const float* __restrict__ x,
                  const float* __restrict__ w,
                  const float* __restrict__ bias,
                  float* __restrict__ out) {
    float* c1v   = smem;                 // 128 (16B aligned)
    float* c2v   = c1v + 128;            // 128
    float* rdiag = c2v + 128;            // 128
    float* AO    = rdiag + 128;          // N_*LD  (original v1, full)
    float* twv   = AO + N_ * LD;         // WPC tap weights
    int*   tkey  = (int*)(twv + WPC);
    __shared__ int s_ntap;

    const int tid = threadIdx.x;

    // ---- Phase 0: compact nonzero taps of this output channel (warp 0) ----
    {
        const int c = blockIdx.x % C_;
        if (tid < 32) {
            int cnt = 0;
            for (int base = 0; base < WPC; base += 32) {
                const int idx = base + tid;
                const float val = (idx < WPC) ? __ldg(&w[c * WPC + idx]) : 0.0f;
                const unsigned msk = __ballot_sync(0xffffffffu, val != 0.0f);
                if (val != 0.0f) {
                    const int pos = cnt + __popc(msk & ((1u << tid) - 1u));
                    const int ci = idx / (KS * KS);
                    const int r  = idx % (KS * KS);
                    twv[pos]  = val;
                    tkey[pos] = (ci << 16) | ((r / KS) << 8) | (r % KS);
                }
                cnt += __popc(msk);
            }
            if (tid == 0) s_ntap = cnt;
        }
    }
    __syncthreads();

    // ---- Phase 1: conv -> AO ----
    {
        const int b = blockIdx.x / C_;
        const int c = blockIdx.x % C_;
        const float bc = __ldg(&bias[c]);
        const int nt = s_ntap;
        const float* __restrict__ xb = x + (size_t)b * C_ * NPIX;
        for (int p = tid; p < NPIX; p += T_) {
            const int pi = p / N_;
            const int pj = p - pi * N_;
            float acc = bc;
            for (int t = 0; t < nt; ++t) {
                const int key = tkey[t];
                const int ci = key >> 16;
                const int ki = (key >> 8) & 255;
                const int kj = key & 255;
                const int ii = pi + ki - HALO;
                const int jj = pj + kj - HALO;
                if (ii >= 0 && ii < N_ && jj >= 0 && jj < N_)
                    acc += twv[t] * __ldg(&xb[(ci * N_ + ii) * N_ + jj]);
            }
            AO[pi * LD + pj] = acc;
        }
    }
    __syncthreads();

    // ---- span assignment (j0-sorted: warps have uniform j0) ----
    int i, j0;
    if (tid < 112)       { i = tid;        j0 = 0;  }
    else if (tid < 192)  { i = tid - 80;   j0 = 32; }
    else if (tid < 240)  { i = tid - 128;  j0 = 64; }
    else                 { i = tid - 144;  j0 = 96; }

    // ---- load my span into packed registers ----
    ull areg2[EPT / 2];
    {
        const int len = min(EPT, i + 1 - j0);
        #pragma unroll
        for (int k = 0; k < EPT; k += 2) {
            const float a0 = (k < len)     ? AO[i * LD + j0 + k]     : 0.0f;
            const float a1 = (k + 1 < len) ? AO[i * LD + j0 + k + 1] : 0.0f;
            areg2[k >> 1] = pk2(a0, a1);
        }
    }

    // ---- Phase 2: rank-2 symmetric sweep, 56 double-pivots ----
    for (int p = 0; p < N_; p += 2) {
        const int kp = p - j0;          // ALWAYS EVEN; may be out of [0,EPT)
        const int kq = kp >> 1;
        const bool rp = (i == p);
        const bool rq = (i == p + 1);
        // publish pivot columns p (c1v) and p+1 (c2v), pre-step values
        if (rp) {
            const int len = min(EPT, i + 1 - j0);
            #pragma unroll
            for (int k = 0; k < EPT; k += 2) {
                const ull v = areg2[k >> 1];
                if (k < len)     c1v[j0 + k]     = lo32(v);
                if (k + 1 < len) c1v[j0 + k + 1] = hi32(v);
            }
        } else if (rq) {
            const int len = min(EPT, i + 1 - j0);
            #pragma unroll
            for (int k = 0; k < EPT; k += 2) {
                const ull v = areg2[k >> 1];
                if (k < len)     c2v[j0 + k]     = lo32(v);
                if (k + 1 < len) c2v[j0 + k + 1] = hi32(v);
            }
        } else if (i > p + 1 && kp >= 0 && kp < EPT) {
            #pragma unroll
            for (int q = 0; q < EPT / 2; ++q)
                if (q == kq) {
                    const ull v = areg2[q];
                    c1v[i] = lo32(v);      // element (i, p)
                    c2v[i] = hi32(v);      // element (i, p+1)
                }
        }
        __syncthreads();
        const float d11 = c1v[p];
        const float d12 = c2v[p];
        const float d22 = c2v[p + 1];
        const float det  = d11 * d22 - d12 * d12;
        const float rdet = 1.0f / det;
        if (tid == p) {                  // thread (i=p, j0=0) always exists
            rdiag[p]     = rsqrtf(d11);
            rdiag[p + 1] = rsqrtf(det / d11);
        }
        // unified coefficients (generic g1,g2; pivot rows via SEL)
        const float c1i = c1v[i];
        const float c2i = c2v[i];
        const float g1 = (c1i * d22 - c2i * d12) * rdet;
        const float g2 = (c2i * d11 - c1i * d12) * rdet;
        const float a12 = d12 * rdet;
        const float u1 = rp ? (1.0f - d22 * rdet) : (rq ? a12 : g1);
        const float u2 = rp ? a12 : (rq ? (1.0f - d11 * rdet) : g2);
        // uniform bulk update (all threads)
        const ull nu1 = pk2(-u1, -u1);
        const ull nu2 = pk2(-u2, -u2);
        const ulonglong2* __restrict__ C1 = (const ulonglong2*)(c1v + j0);
        const ulonglong2* __restrict__ C2 = (const ulonglong2*)(c2v + j0);
        #pragma unroll
        for (int k = 0; k < EPT; k += 4) {
            const ulonglong2 w1 = C1[k >> 2];
            const ulonglong2 w2 = C2[k >> 2];
            FFMA2(areg2[k >> 1],       nu2, w2.x);
            FFMA2(areg2[k >> 1],       nu1, w1.x);
            FFMA2(areg2[(k >> 1) + 1], nu2, w2.y);
            FFMA2(areg2[(k >> 1) + 1], nu1, w1.y);
        }
        // single-ull fixup for columns p (lo) and p+1 (hi) at pair kq
        if (i >= p && kp >= 0 && kp < EPT) {
            const float f1 = rp ? (-d22 * rdet) : (rq ? a12 : g1);
            const float f2 = rq ? (-d11 * rdet) : g2;
            const ull fv = pk2(f1, f2);
            #pragma unroll
            for (int q = 0; q < EPT / 2; ++q)
                if (q == kq) areg2[q] = fv;
        }
        __syncthreads();
    }

    // ---- Phase 3: fused elementwise output (both mirrors per element) ----
    {
        float* __restrict__ O = out + (size_t)blockIdx.x * NPIX;
        const int len = min(EPT, i + 1 - j0);
        const float ri = rdiag[i];
        #pragma unroll
        for (int k = 0; k < EPT; ++k) {
            if (k < len) {
                const int j = j0 + k;
                const ull pv = areg2[k >> 1];
                const float ainv = -((k & 1) ? hi32(pv) : lo32(pv));
                const float rj = rdiag[j];
                const float alo = AO[i * LD + j];
                const float ahi = AO[j * LD + i];
                const float u = fmaf(ainv, ri, 1.0f);
                const float v = fmaf(ainv, rj, 1.0f);
                O[i * N_ + j] = alo * u * u;
                O[j * N_ + i] = ahi * v * v;
            }
        }
    }
}

// ---------------------------------------------------------------------------
extern "C" void kernel_launch(void* const* d_in, const int* in_sizes, int n_in,
                              void* d_out, int out_size) {
    const float* x1   = (const float*)d_in[0];
    const float* w    = (const float*)d_in[1];
    const float* bias = (const float*)d_in[2];
    float* out = (float*)d_out;
    (void)in_sizes; (void)n_in; (void)out_size;

    static const int SMEM_BYTES =
        (int)((384 + N_ * LD + WPC) * sizeof(float) + WPC * sizeof(int));

    cudaFuncSetAttribute(fused_kernel,
                         cudaFuncAttributeMaxDynamicSharedMemorySize,
                         SMEM_BYTES);

    fused_kernel<<<NMAT, T_, SMEM_BYTES>>>(x1, w, bias, out);
}